// round 4
// baseline (speedup 1.0000x reference)
#include <cuda_runtime.h>
#include <math.h>

#define Dm 256
#define Bg 256
#define SH 16
#define CHUNK 512
#define TILE 16

__device__ int   g_off[Bg + 1];
__device__ float g_As[SH * 260];
__device__ float g_cmax[Bg * 4 * SH];
__device__ float g_csum[Bg * 4 * SH];
__device__ float g_cy[Bg * 4 * SH * Dm];        // 16 MB scratch
__device__ float g_W2T[4 * 256 * 256];          // [h][j][i]
__device__ float g_cAtt[256];
__device__ float g_fc1T[1024 * 256];            // [j][i]
__device__ float g_fc2T[256 * 256];             // [j][i]

// ---------------- setup: prefix offsets, q = seeds@WqT+bq, A = scale*(q . Wk) ----
__global__ __launch_bounds__(256) void k_setup(const int* __restrict__ cnt,
                                               const float* __restrict__ seeds,
                                               const float* __restrict__ inW,
                                               const float* __restrict__ inB)
{
    __shared__ float ss[4 * Dm];
    __shared__ float qs[4 * Dm];
    __shared__ int   sc[256];
    int t = threadIdx.x;

    int c = cnt[t]; sc[t] = c; __syncthreads();
    #pragma unroll
    for (int d = 1; d < 256; d <<= 1) {
        int v = (t >= d) ? sc[t - d] : 0; __syncthreads();
        sc[t] += v; __syncthreads();
    }
    g_off[t + 1] = sc[t];
    if (t == 0) g_off[0] = 0;

    for (int i = t; i < 4 * Dm; i += 256) ss[i] = seeds[i];
    __syncthreads();

    // q[s][t] = seeds[s] . Wq[t,:] + bq[t]
    float qa[4] = {0.f, 0.f, 0.f, 0.f};
    const float4* W4 = (const float4*)inW;       // Wq rows first
    const float4* S4 = (const float4*)ss;
    for (int j = 0; j < 64; j++) {
        float4 w = W4[t * 64 + j];
        #pragma unroll
        for (int s = 0; s < 4; s++) {
            float4 sv = S4[s * 64 + j];
            qa[s] += w.x * sv.x + w.y * sv.y + w.z * sv.z + w.w * sv.w;
        }
    }
    #pragma unroll
    for (int s = 0; s < 4; s++) qs[s * Dm + t] = qa[s] + inB[t];
    __syncthreads();

    // A[s*4+h][t] = 0.125 * sum_{dh} q[s][h*64+dh] * Wk[h*64+dh][t]
    const float* Wk = inW + 65536;
    float a[16];
    #pragma unroll
    for (int i = 0; i < 16; i++) a[i] = 0.f;
    #pragma unroll
    for (int h = 0; h < 4; h++)
        for (int dh = 0; dh < 64; dh++) {
            int r = h * 64 + dh;
            float wv = Wk[r * Dm + t];
            #pragma unroll
            for (int s = 0; s < 4; s++) a[s * 4 + h] += qs[s * Dm + r] * wv;
        }
    #pragma unroll
    for (int sh = 0; sh < 16; sh++) g_As[sh * 260 + t] = a[sh] * 0.125f;
}

// ---------------- transposes into device globals (no host symbol lookups) -------
__global__ void k_tr1(const float* __restrict__ src)   // fc1_w [256][1024] -> g_fc1T [1024][256]
{
    __shared__ float tile[32][33];
    int c0 = blockIdx.x * 32, r0 = blockIdx.y * 32;
    int tx = threadIdx.x, ty = threadIdx.y;
    #pragma unroll
    for (int k = 0; k < 4; k++)
        tile[ty + k * 8][tx] = src[(r0 + ty + k * 8) * 1024 + c0 + tx];
    __syncthreads();
    #pragma unroll
    for (int k = 0; k < 4; k++)
        g_fc1T[(c0 + ty + k * 8) * 256 + r0 + tx] = tile[tx][ty + k * 8];
}

__global__ void k_tr2(const float* __restrict__ src)   // fc2_w [256][256] -> g_fc2T [256][256]
{
    __shared__ float tile[32][33];
    int c0 = blockIdx.x * 32, r0 = blockIdx.y * 32;
    int tx = threadIdx.x, ty = threadIdx.y;
    #pragma unroll
    for (int k = 0; k < 4; k++)
        tile[ty + k * 8][tx] = src[(r0 + ty + k * 8) * 256 + c0 + tx];
    __syncthreads();
    #pragma unroll
    for (int k = 0; k < 4; k++)
        g_fc2T[(c0 + ty + k * 8) * 256 + r0 + tx] = tile[tx][ty + k * 8];
}

// ---------------- prep: W2T[h][j][i] = sum_dh Wo[i][h64+dh]*Wv[h64+dh][j]; cAtt --
__global__ __launch_bounds__(256) void k_prep(const float* __restrict__ inW,
                                              const float* __restrict__ inB,
                                              const float* __restrict__ Wo,
                                              const float* __restrict__ bo)
{
    __shared__ float wvs[64 * 16];
    int t = threadIdx.x;
    int hb = blockIdx.x >> 4;
    int j0 = (blockIdx.x & 15) * 16;
    const float* Wv = inW + 2 * 65536;

    #pragma unroll
    for (int k = 0; k < 4; k++) {
        int e = t + k * 256;
        int dh = e >> 4, jj = e & 15;
        wvs[e] = Wv[(hb * 64 + dh) * Dm + j0 + jj];
    }
    __syncthreads();

    const float4* Wo4 = (const float4*)Wo;
    const float4* wv4 = (const float4*)wvs;
    float acc[16];
    #pragma unroll
    for (int i = 0; i < 16; i++) acc[i] = 0.f;
    #pragma unroll
    for (int k = 0; k < 16; k++) {
        float4 w4 = Wo4[t * 64 + hb * 16 + k];
        #pragma unroll
        for (int cc = 0; cc < 4; cc++) {
            float w = (cc == 0) ? w4.x : (cc == 1) ? w4.y : (cc == 2) ? w4.z : w4.w;
            int dh = k * 4 + cc;
            float4 v0 = wv4[dh * 4 + 0], v1 = wv4[dh * 4 + 1];
            float4 v2 = wv4[dh * 4 + 2], v3 = wv4[dh * 4 + 3];
            acc[0] += w * v0.x;  acc[1] += w * v0.y;  acc[2] += w * v0.z;  acc[3] += w * v0.w;
            acc[4] += w * v1.x;  acc[5] += w * v1.y;  acc[6] += w * v1.z;  acc[7] += w * v1.w;
            acc[8] += w * v2.x;  acc[9] += w * v2.y;  acc[10] += w * v2.z; acc[11] += w * v2.w;
            acc[12] += w * v3.x; acc[13] += w * v3.y; acc[14] += w * v3.z; acc[15] += w * v3.w;
        }
    }
    #pragma unroll
    for (int jj = 0; jj < 16; jj++)
        g_W2T[(hb * 256 + j0 + jj) * 256 + t] = acc[jj];

    if (blockIdx.x == 0) {
        __syncthreads();
        wvs[t] = inB[512 + t];                   // bv
        __syncthreads();
        float a = bo[t];
        for (int j = 0; j < 64; j++) {
            float4 w = Wo4[t * 64 + j];
            a += w.x * wvs[4 * j] + w.y * wvs[4 * j + 1] + w.z * wvs[4 * j + 2] + w.w * wvs[4 * j + 3];
        }
        g_cAtt[t] = a;
    }
}

// ---------------- attention: per-chunk online softmax + weighted sums -----------
__global__ __launch_bounds__(256, 3) void k_attn(const float* __restrict__ X)
{
    __shared__ float xs[TILE * 260];        // 16 rows, 65-float4 stride
    __shared__ float As[SH * 260];
    __shared__ float scoreS[TILE * 17];
    __shared__ float scoreE[TILE * 16];
    __shared__ float runm[16], runs[16], rfac[16];

    float4* xs4 = (float4*)xs;
    float4* As4 = (float4*)As;

    int t = threadIdx.x;
    int bid = blockIdx.x;
    int b = bid >> 2, c = bid & 3;
    int off = g_off[b];
    int count = g_off[b + 1] - off;
    int cstart = c * CHUNK;
    if (cstart >= count) return;
    int cend = min(count, cstart + CHUNK);

    for (int e = t; e < SH * 260; e += 256) As[e] = g_As[e];
    if (t < 16) { runm[t] = -1e30f; runs[t] = 0.f; }

    float y[16];
    #pragma unroll
    for (int i = 0; i < 16; i++) y[i] = 0.f;

    const float4* X4 = (const float4*)X;
    __syncthreads();

    for (int n0 = cstart; n0 < cend; n0 += TILE) {
        int tn = min(TILE, cend - n0);
        const float4* xb = X4 + (size_t)(off + n0) * 64;
        for (int e = t; e < tn * 64; e += 256)
            xs4[(e >> 6) * 65 + (e & 63)] = xb[e];
        __syncthreads();

        // scores: thread -> (node n = t>>4, seed-head sh = t&15)
        {
            int n = t >> 4, sh = t & 15;
            if (n < tn) {
                const float4* xr = xs4 + n * 65;
                const float4* ar = As4 + sh * 65;
                float s0 = 0.f, s1 = 0.f;
                #pragma unroll 8
                for (int j = 0; j < 64; j += 2) {
                    float4 x0 = xr[j],     u0 = ar[j];
                    float4 x1 = xr[j + 1], u1 = ar[j + 1];
                    s0 += x0.x * u0.x + x0.y * u0.y + x0.z * u0.z + x0.w * u0.w;
                    s1 += x1.x * u1.x + x1.y * u1.y + x1.z * u1.z + x1.w * u1.w;
                }
                scoreS[n * 17 + sh] = s0 + s1;
            }
        }
        __syncthreads();

        if (t < 16) {
            float m0 = -1e30f, m1 = -1e30f;
            for (int n = 0; n + 1 < tn; n += 2) {
                m0 = fmaxf(m0, scoreS[n * 17 + t]);
                m1 = fmaxf(m1, scoreS[(n + 1) * 17 + t]);
            }
            if (tn & 1) m0 = fmaxf(m0, scoreS[(tn - 1) * 17 + t]);
            float nm = fmaxf(runm[t], fmaxf(m0, m1));
            float rf = __expf(runm[t] - nm);
            float s0 = 0.f, s1 = 0.f;
            for (int n = 0; n + 1 < tn; n += 2) {
                float e0 = __expf(scoreS[n * 17 + t] - nm);
                float e1 = __expf(scoreS[(n + 1) * 17 + t] - nm);
                scoreE[n * 16 + t] = e0;
                scoreE[(n + 1) * 16 + t] = e1;
                s0 += e0; s1 += e1;
            }
            if (tn & 1) {
                float e0 = __expf(scoreS[(tn - 1) * 17 + t] - nm);
                scoreE[(tn - 1) * 16 + t] = e0;
                s0 += e0;
            }
            runs[t] = runs[t] * rf + s0 + s1;
            runm[t] = nm;
            rfac[t] = rf;
        }
        __syncthreads();

        #pragma unroll
        for (int sh = 0; sh < 16; sh++) y[sh] *= rfac[sh];

        const float4* eE = (const float4*)scoreE;
        #pragma unroll 8
        for (int n = 0; n < tn; n++) {
            float xv = xs[n * 260 + t];
            float4 e0 = eE[n * 4], e1 = eE[n * 4 + 1], e2 = eE[n * 4 + 2], e3 = eE[n * 4 + 3];
            y[0] += e0.x * xv;  y[1] += e0.y * xv;  y[2] += e0.z * xv;  y[3] += e0.w * xv;
            y[4] += e1.x * xv;  y[5] += e1.y * xv;  y[6] += e1.z * xv;  y[7] += e1.w * xv;
            y[8] += e2.x * xv;  y[9] += e2.y * xv;  y[10] += e2.z * xv; y[11] += e2.w * xv;
            y[12] += e3.x * xv; y[13] += e3.y * xv; y[14] += e3.z * xv; y[15] += e3.w * xv;
        }
        __syncthreads();
    }

    if (t < 16) {
        g_cmax[bid * 16 + t] = runm[t];
        g_csum[bid * 16 + t] = runs[t];
    }
    #pragma unroll
    for (int sh = 0; sh < 16; sh++)
        g_cy[(bid * 16 + sh) * 256 + t] = y[sh];
}

// ---------------- combine: lse-merge chunks, attended = W2T.y + cAtt, fc1/2 -----
__global__ __launch_bounds__(256) void k_comb(float* __restrict__ out,
                                              const float* __restrict__ fc1b,
                                              const float* __restrict__ fc2b)
{
    __shared__ float ysP[8192];     // [g][h][j][s] as float4 over s
    __shared__ float att[2048];
    __shared__ float hbuf[512];
    __shared__ float scl[128];
    __shared__ float itot[32];

    int t = threadIdx.x;
    int b0 = blockIdx.x * 2;

    for (int g = 0; g < 2; g++) {
        int b = b0 + g;
        int cntb = g_off[b + 1] - g_off[b];
        int nch = min(4, (cntb + CHUNK - 1) >> 9);
        if (t < 16) {
            float M = -1e30f;
            for (int c = 0; c < nch; c++) M = fmaxf(M, g_cmax[(b * 4 + c) * 16 + t]);
            float tot = 0.f;
            #pragma unroll
            for (int c = 0; c < 4; c++) {
                float e = 0.f;
                if (c < nch) {
                    float s = g_csum[(b * 4 + c) * 16 + t];
                    if (s > 0.f) { e = __expf(g_cmax[(b * 4 + c) * 16 + t] - M); tot += e * s; }
                }
                scl[(g * 4 + c) * 16 + t] = e;
            }
            itot[g * 16 + t] = 1.f / tot;
        }
    }
    __syncthreads();

    for (int g = 0; g < 2; g++) {
        int b = b0 + g;
        #pragma unroll
        for (int sh = 0; sh < 16; sh++) {
            float acc = 0.f;
            #pragma unroll
            for (int c = 0; c < 4; c++)
                acc += scl[(g * 4 + c) * 16 + sh] * g_cy[((b * 4 + c) * 16 + sh) * 256 + t];
            float yv = acc * itot[g * 16 + sh];
            // sh = s*4 + h  ->  store y[g][h][j=t][s]
            ysP[(((g * 4 + (sh & 3)) * 256 + t) << 2) + (sh >> 2)] = yv;
        }
    }
    __syncthreads();

    // attended: a[g*4+s] for column i=t
    float a[8];
    float ca = g_cAtt[t];
    #pragma unroll
    for (int i = 0; i < 8; i++) a[i] = ca;
    #pragma unroll
    for (int h = 0; h < 4; h++) {
        const float*  wp = g_W2T + h * 65536 + t;
        const float4* y0 = (const float4*)ysP + (0 * 4 + h) * 256;
        const float4* y1 = (const float4*)ysP + (1 * 4 + h) * 256;
        #pragma unroll 4
        for (int j = 0; j < 256; j++) {
            float w = wp[j * 256];
            float4 p0 = y0[j], p1 = y1[j];
            a[0] += w * p0.x; a[1] += w * p0.y; a[2] += w * p0.z; a[3] += w * p0.w;
            a[4] += w * p1.x; a[5] += w * p1.y; a[6] += w * p1.z; a[7] += w * p1.w;
        }
    }
    #pragma unroll
    for (int s = 0; s < 4; s++) {
        att[s * 256 + t] = a[s];
        att[1024 + s * 256 + t] = a[4 + s];
    }
    __syncthreads();

    float pre0 = fc1b[t], pre1 = fc1b[t];
    #pragma unroll 4
    for (int j = 0; j < 1024; j++) {
        float w = g_fc1T[j * 256 + t];
        pre0 += w * att[j];
        pre1 += w * att[1024 + j];
    }
    hbuf[t]       = 0.5f * pre0 * (1.f + erff(pre0 * 0.70710678118f));
    hbuf[256 + t] = 0.5f * pre1 * (1.f + erff(pre1 * 0.70710678118f));
    __syncthreads();

    float o0 = fc2b[t], o1 = fc2b[t];
    #pragma unroll 4
    for (int j = 0; j < 256; j++) {
        float w = g_fc2T[j * 256 + t];
        o0 += w * hbuf[j];
        o1 += w * hbuf[256 + j];
    }
    out[b0 * 256 + t] = o0;
    out[(b0 + 1) * 256 + t] = o1;
}

// ---------------- launch: kernel launches ONLY ----------------------------------
extern "C" void kernel_launch(void* const* d_in, const int* in_sizes, int n_in,
                              void* d_out, int out_size)
{
    const float* X     = (const float*)d_in[0];
    const int*   cnt   = (const int*)  d_in[1];
    const float* seeds = (const float*)d_in[2];
    const float* inW   = (const float*)d_in[3];
    const float* inB   = (const float*)d_in[4];
    const float* outW  = (const float*)d_in[5];
    const float* outB  = (const float*)d_in[6];
    const float* fc1w  = (const float*)d_in[7];
    const float* fc1b  = (const float*)d_in[8];
    const float* fc2w  = (const float*)d_in[9];
    const float* fc2b  = (const float*)d_in[10];
    float* out = (float*)d_out;

    k_setup<<<1, 256>>>(cnt, seeds, inW, inB);
    k_tr1<<<dim3(32, 8), dim3(32, 8)>>>(fc1w);
    k_tr2<<<dim3(8, 8),  dim3(32, 8)>>>(fc2w);
    k_prep<<<64, 256>>>(inW, inB, outW, outB);
    k_attn<<<1024, 256>>>(X);
    k_comb<<<128, 256>>>(out, fc1b, fc2b);
}

// round 5
// speedup vs baseline: 1.2641x; 1.2641x over previous
#include <cuda_runtime.h>
#include <math.h>

#define Dm 256
#define Bg 256
#define SH 16
#define CHUNK 512
#define TILE 32

__device__ int   g_off[Bg + 1];
__device__ float g_As[SH * 260];
__device__ float g_cmax[Bg * 4 * SH];
__device__ float g_csum[Bg * 4 * SH];
__device__ float g_cy[Bg * 4 * SH * Dm];        // 16 MB scratch
__device__ float g_W2T[4 * 256 * 256];          // [h][j][i]
__device__ float g_cAtt[256];
__device__ float g_fc1T[1024 * 256];            // [j][i]
__device__ float g_fc2T[256 * 256];             // [j][i]

// ---- cp.async helpers ----------------------------------------------------------
__device__ __forceinline__ void cp_async16(void* dst_smem, const void* src_gmem) {
    unsigned sa = (unsigned)__cvta_generic_to_shared(dst_smem);
    asm volatile("cp.async.cg.shared.global [%0], [%1], 16;\n" :: "r"(sa), "l"(src_gmem));
}
#define CP_COMMIT() asm volatile("cp.async.commit_group;\n" ::: "memory")
#define CP_WAIT0()  asm volatile("cp.async.wait_group 0;\n" ::: "memory")

// ---------------- setup: prefix offsets, q = seeds@WqT+bq, A = scale*(q . Wk) ----
__global__ __launch_bounds__(256) void k_setup(const int* __restrict__ cnt,
                                               const float* __restrict__ seeds,
                                               const float* __restrict__ inW,
                                               const float* __restrict__ inB)
{
    __shared__ float ss[4 * Dm];
    __shared__ float qs[4 * Dm];
    __shared__ int   sc[256];
    int t = threadIdx.x;

    int c = cnt[t]; sc[t] = c; __syncthreads();
    #pragma unroll
    for (int d = 1; d < 256; d <<= 1) {
        int v = (t >= d) ? sc[t - d] : 0; __syncthreads();
        sc[t] += v; __syncthreads();
    }
    g_off[t + 1] = sc[t];
    if (t == 0) g_off[0] = 0;

    for (int i = t; i < 4 * Dm; i += 256) ss[i] = seeds[i];
    __syncthreads();

    float qa[4] = {0.f, 0.f, 0.f, 0.f};
    const float4* W4 = (const float4*)inW;
    const float4* S4 = (const float4*)ss;
    for (int j = 0; j < 64; j++) {
        float4 w = W4[t * 64 + j];
        #pragma unroll
        for (int s = 0; s < 4; s++) {
            float4 sv = S4[s * 64 + j];
            qa[s] += w.x * sv.x + w.y * sv.y + w.z * sv.z + w.w * sv.w;
        }
    }
    #pragma unroll
    for (int s = 0; s < 4; s++) qs[s * Dm + t] = qa[s] + inB[t];
    __syncthreads();

    const float* Wk = inW + 65536;
    float a[16];
    #pragma unroll
    for (int i = 0; i < 16; i++) a[i] = 0.f;
    #pragma unroll
    for (int h = 0; h < 4; h++)
        for (int dh = 0; dh < 64; dh++) {
            int r = h * 64 + dh;
            float wv = Wk[r * Dm + t];
            #pragma unroll
            for (int s = 0; s < 4; s++) a[s * 4 + h] += qs[s * Dm + r] * wv;
        }
    #pragma unroll
    for (int sh = 0; sh < 16; sh++) g_As[sh * 260 + t] = a[sh] * 0.125f;
}

// ---------------- fused transposes: fc1_w and fc2_w -> [j][i] globals ------------
__global__ void k_tr(const float* __restrict__ fc1w, const float* __restrict__ fc2w)
{
    __shared__ float tile[32][33];
    int bid = blockIdx.x;
    int tx = threadIdx.x, ty = threadIdx.y;
    const float* src; float* dst; int C, c0, r0;
    if (bid < 256) { src = fc1w; dst = g_fc1T; C = 1024; c0 = (bid & 31) * 32; r0 = (bid >> 5) * 32; }
    else { int b2 = bid - 256; src = fc2w; dst = g_fc2T; C = 256; c0 = (b2 & 7) * 32; r0 = (b2 >> 3) * 32; }
    #pragma unroll
    for (int k = 0; k < 4; k++)
        tile[ty + k * 8][tx] = src[(r0 + ty + k * 8) * C + c0 + tx];
    __syncthreads();
    #pragma unroll
    for (int k = 0; k < 4; k++)
        dst[(c0 + ty + k * 8) * 256 + r0 + tx] = tile[tx][ty + k * 8];
}

// ---------------- prep: W2T[h][j][i] = sum_dh Wo[i][h64+dh]*Wv[h64+dh][j]; cAtt --
__global__ __launch_bounds__(256) void k_prep(const float* __restrict__ inW,
                                              const float* __restrict__ inB,
                                              const float* __restrict__ Wo,
                                              const float* __restrict__ bo)
{
    __shared__ float wvs[256];              // [dh 0..63][jj 0..3]
    int t = threadIdx.x;
    int hb = blockIdx.x >> 6;               // 0..3
    int j0 = (blockIdx.x & 63) * 4;         // 0..252
    const float* Wv = inW + 2 * 65536;

    { int dh = t >> 2, jj = t & 3;
      wvs[t] = Wv[(hb * 64 + dh) * Dm + j0 + jj]; }
    __syncthreads();

    const float4* Wo4 = (const float4*)Wo;
    const float4* wv4 = (const float4*)wvs;
    float a0 = 0.f, a1 = 0.f, a2 = 0.f, a3 = 0.f;
    #pragma unroll
    for (int k = 0; k < 16; k++) {
        float4 w = Wo4[t * 64 + hb * 16 + k];
        float4 v0 = wv4[k * 4 + 0], v1 = wv4[k * 4 + 1];
        float4 v2 = wv4[k * 4 + 2], v3 = wv4[k * 4 + 3];
        a0 += w.x * v0.x + w.y * v1.x + w.z * v2.x + w.w * v3.x;
        a1 += w.x * v0.y + w.y * v1.y + w.z * v2.y + w.w * v3.y;
        a2 += w.x * v0.z + w.y * v1.z + w.z * v2.z + w.w * v3.z;
        a3 += w.x * v0.w + w.y * v1.w + w.z * v2.w + w.w * v3.w;
    }
    g_W2T[(hb * 256 + j0 + 0) * 256 + t] = a0;
    g_W2T[(hb * 256 + j0 + 1) * 256 + t] = a1;
    g_W2T[(hb * 256 + j0 + 2) * 256 + t] = a2;
    g_W2T[(hb * 256 + j0 + 3) * 256 + t] = a3;

    if (blockIdx.x == 0) {
        __syncthreads();
        wvs[t] = inB[512 + t];               // bv
        __syncthreads();
        float a = bo[t];
        for (int j = 0; j < 64; j++) {
            float4 w = Wo4[t * 64 + j];
            a += w.x * wvs[4 * j] + w.y * wvs[4 * j + 1] + w.z * wvs[4 * j + 2] + w.w * wvs[4 * j + 3];
        }
        g_cAtt[t] = a;
    }
}

// ---------------- attention: pipelined tiles, blocked scores, online softmax ----
// dyn smem floats:
//   xs     [0, 16640)      2 bufs x 32 rows x 260 (65-f4 row stride)
//   As     [16640, 20800)
//   sp0    [20800, 21344)  score partials kh=0, [32][17]
//   sp1    [21344, 21888)  score partials kh=1
//   scE    [21888, 22400)  exp weights [32][16]
//   rfac   [22400, 22416)
#define ATTN_SMEM_F 22416
__global__ __launch_bounds__(256, 2) void k_attn(const float* __restrict__ X)
{
    extern __shared__ __align__(16) float sm[];
    float4* xs4  = (float4*)sm;
    float*  xs   = sm;
    float*  As   = sm + 16640;
    float4* As4  = (float4*)As;
    float*  sp0  = sm + 20800;
    float*  sp1  = sm + 21344;
    float*  scE  = sm + 21888;
    float*  rfac = sm + 22400;

    int t = threadIdx.x;
    int bid = blockIdx.x;
    int b = bid >> 2, c = bid & 3;
    int off = g_off[b];
    int count = g_off[b + 1] - off;
    int cstart = c * CHUNK;
    if (cstart >= count) return;
    int cend = min(count, cstart + CHUNK);
    int ntiles = (cend - cstart + TILE - 1) >> 5;

    for (int e = t; e < SH * 260; e += 256) As[e] = g_As[e];

    const float4* X4 = (const float4*)X;

    // prefetch tile 0 into buffer 0
    {
        int tn0 = min(TILE, cend - cstart);
        for (int e = t; e < tn0 * 64; e += 256)
            cp_async16(&xs4[(e >> 6) * 65 + (e & 63)],
                       &X4[(size_t)(off + cstart + (e >> 6)) * 64 + (e & 63)]);
        CP_COMMIT();
    }

    float runm = -1e30f, runs = 0.f;
    float y[16];
    #pragma unroll
    for (int i = 0; i < 16; i++) y[i] = 0.f;

    int cb  = t & 127;
    int n0r = (cb >> 3) * 2, n1r = n0r + 1;   // node pair
    int spr = cb & 7;                          // sh pair {spr, spr+8}
    int jb  = (t >> 7) * 32;                   // half-K range
    float* spk = (t >> 7) ? sp1 : sp0;

    for (int i = 0; i < ntiles; i++) {
        CP_WAIT0();
        __syncthreads();
        int bi = i & 1;
        int tn = min(TILE, cend - (cstart + i * TILE));

        if (i + 1 < ntiles) {
            int ns = cstart + (i + 1) * TILE;
            int tnn = min(TILE, cend - ns);
            int bn = (i + 1) & 1;
            for (int e = t; e < tnn * 64; e += 256)
                cp_async16(&xs4[bn * 2080 + (e >> 6) * 65 + (e & 63)],
                           &X4[(size_t)(off + ns + (e >> 6)) * 64 + (e & 63)]);
        }
        CP_COMMIT();

        // ---- score phase: 2 nodes x 2 sh per thread over half-K ----
        {
            const float4* xr0 = xs4 + bi * 2080 + n0r * 65 + jb;
            const float4* xr1 = xs4 + bi * 2080 + n1r * 65 + jb;
            const float4* ar0 = As4 + spr * 65 + jb;
            const float4* ar1 = As4 + (spr + 8) * 65 + jb;
            float s00 = 0.f, s01 = 0.f, s10 = 0.f, s11 = 0.f;
            #pragma unroll 8
            for (int j = 0; j < 32; j++) {
                float4 x0 = xr0[j], x1 = xr1[j], a0 = ar0[j], a1 = ar1[j];
                s00 += x0.x * a0.x + x0.y * a0.y + x0.z * a0.z + x0.w * a0.w;
                s01 += x0.x * a1.x + x0.y * a1.y + x0.z * a1.z + x0.w * a1.w;
                s10 += x1.x * a0.x + x1.y * a0.y + x1.z * a0.z + x1.w * a0.w;
                s11 += x1.x * a1.x + x1.y * a1.y + x1.z * a1.z + x1.w * a1.w;
            }
            spk[n0r * 17 + spr]     = s00;
            spk[n0r * 17 + spr + 8] = s01;
            spk[n1r * 17 + spr]     = s10;
            spk[n1r * 17 + spr + 8] = s11;
        }
        __syncthreads();

        // ---- softmax: warp 0, 16 sh x 2 node-halves ----
        if (t < 32) {
            int sh = t & 15;
            int nlo = (t >> 4) * 16;
            int nhi = min(tn, nlo + 16);
            float m = -1e30f;
            for (int n = nlo; n < nhi; n++) {
                float v = sp0[n * 17 + sh] + sp1[n * 17 + sh];
                sp0[n * 17 + sh] = v;
                m = fmaxf(m, v);
            }
            m = fmaxf(m, __shfl_xor_sync(0xffffffffu, m, 16));
            float nm = fmaxf(runm, m);
            float rf = __expf(runm - nm);
            float ssum = 0.f;
            for (int n = nlo; n < nhi; n++) {
                float e = __expf(sp0[n * 17 + sh] - nm);
                scE[n * 16 + sh] = e;
                ssum += e;
            }
            ssum += __shfl_xor_sync(0xffffffffu, ssum, 16);
            runs = runs * rf + ssum;
            runm = nm;
            if (t < 16) rfac[t] = rf;
        }
        __syncthreads();

        // ---- y-pass: thread = column ----
        #pragma unroll
        for (int sh = 0; sh < 16; sh++) y[sh] *= rfac[sh];
        {
            const float4* eE = (const float4*)scE;
            const float* xcol = xs + bi * 8320 + t;
            #pragma unroll 8
            for (int n = 0; n < tn; n++) {
                float xv = xcol[n * 260];
                float4 e0 = eE[n * 4], e1 = eE[n * 4 + 1], e2 = eE[n * 4 + 2], e3 = eE[n * 4 + 3];
                y[0]  += e0.x * xv; y[1]  += e0.y * xv; y[2]  += e0.z * xv; y[3]  += e0.w * xv;
                y[4]  += e1.x * xv; y[5]  += e1.y * xv; y[6]  += e1.z * xv; y[7]  += e1.w * xv;
                y[8]  += e2.x * xv; y[9]  += e2.y * xv; y[10] += e2.z * xv; y[11] += e2.w * xv;
                y[12] += e3.x * xv; y[13] += e3.y * xv; y[14] += e3.z * xv; y[15] += e3.w * xv;
            }
        }
        // next-iteration top barrier doubles as the post-y fence
    }
    __syncthreads();

    if (t < 16) {
        g_cmax[bid * 16 + t] = runm;
        g_csum[bid * 16 + t] = runs;
    }
    #pragma unroll
    for (int sh = 0; sh < 16; sh++)
        g_cy[(bid * 16 + sh) * 256 + t] = y[sh];
}

// ---------------- combine: lse-merge chunks, attended = W2T.y + cAtt, fc1/2 -----
__global__ __launch_bounds__(256) void k_comb(float* __restrict__ out,
                                              const float* __restrict__ fc1b,
                                              const float* __restrict__ fc2b)
{
    __shared__ float ysP[8192];     // [g][h][j][s] as float4 over s
    __shared__ float att[2048];
    __shared__ float hbuf[512];
    __shared__ float scl[128];
    __shared__ float itot[32];

    int t = threadIdx.x;
    int b0 = blockIdx.x * 2;

    for (int g = 0; g < 2; g++) {
        int b = b0 + g;
        int cntb = g_off[b + 1] - g_off[b];
        int nch = min(4, (cntb + CHUNK - 1) >> 9);
        if (t < 16) {
            float M = -1e30f;
            for (int c = 0; c < nch; c++) M = fmaxf(M, g_cmax[(b * 4 + c) * 16 + t]);
            float tot = 0.f;
            #pragma unroll
            for (int c = 0; c < 4; c++) {
                float e = 0.f;
                if (c < nch) {
                    float s = g_csum[(b * 4 + c) * 16 + t];
                    if (s > 0.f) { e = __expf(g_cmax[(b * 4 + c) * 16 + t] - M); tot += e * s; }
                }
                scl[(g * 4 + c) * 16 + t] = e;
            }
            itot[g * 16 + t] = 1.f / tot;
        }
    }
    __syncthreads();

    for (int g = 0; g < 2; g++) {
        int b = b0 + g;
        #pragma unroll
        for (int sh = 0; sh < 16; sh++) {
            float acc = 0.f;
            #pragma unroll
            for (int c = 0; c < 4; c++)
                acc += scl[(g * 4 + c) * 16 + sh] * g_cy[((b * 4 + c) * 16 + sh) * 256 + t];
            float yv = acc * itot[g * 16 + sh];
            ysP[(((g * 4 + (sh & 3)) * 256 + t) << 2) + (sh >> 2)] = yv;
        }
    }
    __syncthreads();

    float a[8];
    float ca = g_cAtt[t];
    #pragma unroll
    for (int i = 0; i < 8; i++) a[i] = ca;
    #pragma unroll
    for (int h = 0; h < 4; h++) {
        const float*  wp = g_W2T + h * 65536 + t;
        const float4* y0 = (const float4*)ysP + (0 * 4 + h) * 256;
        const float4* y1 = (const float4*)ysP + (1 * 4 + h) * 256;
        #pragma unroll 4
        for (int j = 0; j < 256; j++) {
            float w = wp[j * 256];
            float4 p0 = y0[j], p1 = y1[j];
            a[0] += w * p0.x; a[1] += w * p0.y; a[2] += w * p0.z; a[3] += w * p0.w;
            a[4] += w * p1.x; a[5] += w * p1.y; a[6] += w * p1.z; a[7] += w * p1.w;
        }
    }
    #pragma unroll
    for (int s = 0; s < 4; s++) {
        att[s * 256 + t] = a[s];
        att[1024 + s * 256 + t] = a[4 + s];
    }
    __syncthreads();

    float pre0 = fc1b[t], pre1 = fc1b[t];
    #pragma unroll 4
    for (int j = 0; j < 1024; j++) {
        float w = g_fc1T[j * 256 + t];
        pre0 += w * att[j];
        pre1 += w * att[1024 + j];
    }
    hbuf[t]       = 0.5f * pre0 * (1.f + erff(pre0 * 0.70710678118f));
    hbuf[256 + t] = 0.5f * pre1 * (1.f + erff(pre1 * 0.70710678118f));
    __syncthreads();

    float o0 = fc2b[t], o1 = fc2b[t];
    #pragma unroll 4
    for (int j = 0; j < 256; j++) {
        float w = g_fc2T[j * 256 + t];
        o0 += w * hbuf[j];
        o1 += w * hbuf[256 + j];
    }
    out[b0 * 256 + t] = o0;
    out[(b0 + 1) * 256 + t] = o1;
}

// ---------------- launch --------------------------------------------------------
extern "C" void kernel_launch(void* const* d_in, const int* in_sizes, int n_in,
                              void* d_out, int out_size)
{
    const float* X     = (const float*)d_in[0];
    const int*   cnt   = (const int*)  d_in[1];
    const float* seeds = (const float*)d_in[2];
    const float* inW   = (const float*)d_in[3];
    const float* inB   = (const float*)d_in[4];
    const float* outW  = (const float*)d_in[5];
    const float* outB  = (const float*)d_in[6];
    const float* fc1w  = (const float*)d_in[7];
    const float* fc1b  = (const float*)d_in[8];
    const float* fc2w  = (const float*)d_in[9];
    const float* fc2b  = (const float*)d_in[10];
    float* out = (float*)d_out;

    cudaFuncSetAttribute(k_attn, cudaFuncAttributeMaxDynamicSharedMemorySize,
                         ATTN_SMEM_F * 4);

    k_setup<<<1, 256>>>(cnt, seeds, inW, inB);
    k_tr<<<320, dim3(32, 8)>>>(fc1w, fc2w);
    k_prep<<<256, 256>>>(inW, inB, outW, outB);
    k_attn<<<1024, 256, ATTN_SMEM_F * 4>>>(X);
    k_comb<<<128, 256>>>(out, fc1b, fc2b);
}

// round 7
// speedup vs baseline: 1.6110x; 1.2744x over previous
#include <cuda_runtime.h>
#include <math.h>

#define Dm 256
#define Bg 256
#define SH 16
#define CHUNK 512
#define TILE 32

__device__ int   g_off[Bg + 1];
__device__ float g_As[SH * 260];
__device__ float g_cmax[Bg * 4 * SH];
__device__ float g_csum[Bg * 4 * SH];
__device__ float g_cy[Bg * 4 * SH * Dm];        // 16 MB scratch
__device__ float g_W2T[4 * 256 * 256];          // [h][j][i]
__device__ float g_cAtt[256];
__device__ float g_fc1T[1024 * 256];            // [j][i]
__device__ float g_fc2T[256 * 256];             // [j][i]

// ---- cp.async helpers ----------------------------------------------------------
__device__ __forceinline__ void cp_async16(void* dst_smem, const void* src_gmem) {
    unsigned sa = (unsigned)__cvta_generic_to_shared(dst_smem);
    asm volatile("cp.async.cg.shared.global [%0], [%1], 16;\n" :: "r"(sa), "l"(src_gmem));
}
#define CP_COMMIT() asm volatile("cp.async.commit_group;\n" ::: "memory")
#define CP_WAIT0()  asm volatile("cp.async.wait_group 0;\n" ::: "memory")

// ---------------- fused prologue -------------------------------------------------
// blocks [0,32):  A columns (8 each), redundant q
// block  32:      prefix offsets + cAtt
// blocks [33,289): W2T tiles (hb, 4 j-cols)
// blocks [289,609): fc1/fc2 transposes
__global__ __launch_bounds__(256) void k_pro(const int* __restrict__ cnt,
                                             const float* __restrict__ seeds,
                                             const float* __restrict__ inW,
                                             const float* __restrict__ inB,
                                             const float* __restrict__ Wo,
                                             const float* __restrict__ bo,
                                             const float* __restrict__ fc1w,
                                             const float* __restrict__ fc2w)
{
    __shared__ float sbuf[2112];
    int bid = blockIdx.x;
    int t = threadIdx.x;

    if (bid < 32) {
        // ---- A slice: cols [bid*8, bid*8+8) ----
        float* ss = sbuf;          // 1024
        float* qs = sbuf + 1024;   // 1024
        for (int i = t; i < 1024; i += 256) ss[i] = seeds[i];
        __syncthreads();
        float qa[4] = {0.f, 0.f, 0.f, 0.f};
        const float4* W4 = (const float4*)inW;
        const float4* S4 = (const float4*)ss;
        for (int j = 0; j < 64; j++) {
            float4 w = W4[t * 64 + j];
            #pragma unroll
            for (int s = 0; s < 4; s++) {
                float4 sv = S4[s * 64 + j];
                qa[s] += w.x * sv.x + w.y * sv.y + w.z * sv.z + w.w * sv.w;
            }
        }
        #pragma unroll
        for (int s = 0; s < 4; s++) qs[s * 256 + t] = qa[s] + inB[t];
        __syncthreads();
        if (t < 128) {
            int sh = t >> 3, col = bid * 8 + (t & 7);
            int s = sh >> 2, h = sh & 3;
            const float* Wk = inW + 65536;
            const float* qrow = qs + s * 256 + h * 64;
            const float* wcol = Wk + (h * 64) * 256 + col;
            float acc = 0.f;
            #pragma unroll 8
            for (int dh = 0; dh < 64; dh++)
                acc += qrow[dh] * wcol[dh * 256];
            g_As[sh * 260 + col] = acc * 0.125f;
        }
    } else if (bid == 32) {
        // ---- prefix offsets ----
        int* sc = (int*)sbuf;
        int c = cnt[t]; sc[t] = c; __syncthreads();
        #pragma unroll
        for (int d = 1; d < 256; d <<= 1) {
            int v = (t >= d) ? sc[t - d] : 0; __syncthreads();
            sc[t] += v; __syncthreads();
        }
        g_off[t + 1] = sc[t];
        if (t == 0) g_off[0] = 0;
        // ---- cAtt = Wo . bv + bo ----
        float* bvs = sbuf + 256;
        bvs[t] = inB[512 + t];
        __syncthreads();
        const float4* Wo4 = (const float4*)Wo;
        const float4* bv4 = (const float4*)bvs;
        float a = bo[t];
        for (int j = 0; j < 64; j++) {
            float4 w = Wo4[t * 64 + j], v = bv4[j];
            a += w.x * v.x + w.y * v.y + w.z * v.z + w.w * v.w;
        }
        g_cAtt[t] = a;
    } else if (bid < 289) {
        // ---- W2T[h][j][i] = sum_dh Wo[i][h*64+dh] * Wv[h*64+dh][j] ----
        float* wvs = sbuf;         // 256: [dh 0..63][jj 0..3]
        int b2 = bid - 33;
        int hb = b2 >> 6;
        int j0 = (b2 & 63) * 4;
        const float* Wv = inW + 2 * 65536;
        { int dh = t >> 2, jj = t & 3;
          wvs[t] = Wv[(hb * 64 + dh) * Dm + j0 + jj]; }
        __syncthreads();
        const float4* Wo4 = (const float4*)Wo;
        const float4* wv4 = (const float4*)wvs;
        float a0 = 0.f, a1 = 0.f, a2 = 0.f, a3 = 0.f;
        #pragma unroll
        for (int k = 0; k < 16; k++) {
            float4 w = Wo4[t * 64 + hb * 16 + k];
            float4 v0 = wv4[k * 4 + 0], v1 = wv4[k * 4 + 1];
            float4 v2 = wv4[k * 4 + 2], v3 = wv4[k * 4 + 3];
            a0 += w.x * v0.x + w.y * v1.x + w.z * v2.x + w.w * v3.x;
            a1 += w.x * v0.y + w.y * v1.y + w.z * v2.y + w.w * v3.y;
            a2 += w.x * v0.z + w.y * v1.z + w.z * v2.z + w.w * v3.z;
            a3 += w.x * v0.w + w.y * v1.w + w.z * v2.w + w.w * v3.w;
        }
        g_W2T[(hb * 256 + j0 + 0) * 256 + t] = a0;
        g_W2T[(hb * 256 + j0 + 1) * 256 + t] = a1;
        g_W2T[(hb * 256 + j0 + 2) * 256 + t] = a2;
        g_W2T[(hb * 256 + j0 + 3) * 256 + t] = a3;
    } else {
        // ---- transposes ----
        float (*tile)[33] = (float (*)[33])sbuf;   // 32x33 = 1056
        int b3 = bid - 289;
        int tx = t & 31, ty = t >> 5;
        const float* src; float* dst; int C, c0, r0;
        if (b3 < 256) { src = fc1w; dst = g_fc1T; C = 1024; c0 = (b3 & 31) * 32; r0 = (b3 >> 5) * 32; }
        else { int b4 = b3 - 256; src = fc2w; dst = g_fc2T; C = 256; c0 = (b4 & 7) * 32; r0 = (b4 >> 3) * 32; }
        #pragma unroll
        for (int k = 0; k < 4; k++)
            tile[ty + k * 8][tx] = src[(r0 + ty + k * 8) * C + c0 + tx];
        __syncthreads();
        #pragma unroll
        for (int k = 0; k < 4; k++)
            dst[(c0 + ty + k * 8) * 256 + r0 + tx] = tile[tx][ty + k * 8];
    }
}

// ---------------- attention: pipelined tiles, 4x4 blocked scores ----------------
// dyn smem floats:
//   xs     [0, 16640)      2 bufs x 32 rows x 260 (65-f4 row stride)
//   As     [16640, 20800)
//   scoreS [20800, 21344)  [32][17]
//   scE    [21344, 21856)  [32][16]
//   rfac   [21856, 21872)
#define ATTN_SMEM_F 21872
__global__ __launch_bounds__(256, 2) void k_attn(const float* __restrict__ X)
{
    extern __shared__ __align__(16) float sm[];
    float4* xs4    = (float4*)sm;
    float*  xs     = sm;
    float*  As     = sm + 16640;
    float4* As4    = (float4*)As;
    float*  scoreS = sm + 20800;
    float*  scE    = sm + 21344;
    float*  rfac   = sm + 21856;

    int t = threadIdx.x;
    int bid = blockIdx.x;
    int b = bid >> 2, c = bid & 3;
    int off = g_off[b];
    int count = g_off[b + 1] - off;
    int cstart = c * CHUNK;
    if (cstart >= count) return;
    int cend = min(count, cstart + CHUNK);
    int ntiles = (cend - cstart + TILE - 1) >> 5;

    for (int e = t; e < SH * 260; e += 256) As[e] = g_As[e];

    const float4* X4 = (const float4*)X;

    // prefetch tile 0 into buffer 0
    {
        int tn0 = min(TILE, cend - cstart);
        for (int e = t; e < tn0 * 64; e += 256)
            cp_async16(&xs4[(e >> 6) * 65 + (e & 63)],
                       &X4[(size_t)(off + cstart + (e >> 6)) * 64 + (e & 63)]);
        CP_COMMIT();
    }

    float runm = -1e30f, runs = 0.f;
    float y[16];
    #pragma unroll
    for (int i = 0; i < 16; i++) y[i] = 0.f;

    int kk  = t & 7;          // K-split lane (interleaved f4 idx = kk + 8*j)
    int shg = (t >> 3) & 3;   // sh group of 4
    int ng  = t >> 5;         // node group of 4

    for (int i = 0; i < ntiles; i++) {
        CP_WAIT0();
        __syncthreads();
        int bi = i & 1;
        int tn = min(TILE, cend - (cstart + i * TILE));

        if (i + 1 < ntiles) {
            int ns = cstart + (i + 1) * TILE;
            int tnn = min(TILE, cend - ns);
            int bn = (i + 1) & 1;
            for (int e = t; e < tnn * 64; e += 256)
                cp_async16(&xs4[bn * 2080 + (e >> 6) * 65 + (e & 63)],
                           &X4[(size_t)(off + ns + (e >> 6)) * 64 + (e & 63)]);
        }
        CP_COMMIT();

        // ---- score phase: 4 nodes x 4 sh, K interleaved-split 8 ways ----
        {
            float acc[4][4];
            #pragma unroll
            for (int nn = 0; nn < 4; nn++)
                #pragma unroll
                for (int ss = 0; ss < 4; ss++) acc[nn][ss] = 0.f;
            const float4* xb = xs4 + bi * 2080;
            const float4* ar = As4 + (4 * shg) * 65 + kk;
            const float4* xr = xb + (4 * ng) * 65 + kk;
            #pragma unroll
            for (int j = 0; j < 8; j++) {
                int f4i = 8 * j;
                float4 a0 = ar[f4i], a1 = ar[65 + f4i], a2 = ar[130 + f4i], a3 = ar[195 + f4i];
                #pragma unroll
                for (int nn = 0; nn < 4; nn++) {
                    float4 xv = xr[nn * 65 + f4i];
                    acc[nn][0] += xv.x * a0.x + xv.y * a0.y + xv.z * a0.z + xv.w * a0.w;
                    acc[nn][1] += xv.x * a1.x + xv.y * a1.y + xv.z * a1.z + xv.w * a1.w;
                    acc[nn][2] += xv.x * a2.x + xv.y * a2.y + xv.z * a2.z + xv.w * a2.w;
                    acc[nn][3] += xv.x * a3.x + xv.y * a3.y + xv.z * a3.z + xv.w * a3.w;
                }
            }
            // reduce over kk (lanes 0..7 of each 8-group)
            #pragma unroll
            for (int nn = 0; nn < 4; nn++)
                #pragma unroll
                for (int ss = 0; ss < 4; ss++) {
                    float v = acc[nn][ss];
                    v += __shfl_xor_sync(0xffffffffu, v, 1);
                    v += __shfl_xor_sync(0xffffffffu, v, 2);
                    v += __shfl_xor_sync(0xffffffffu, v, 4);
                    acc[nn][ss] = v;
                }
            if (kk == 0) {
                #pragma unroll
                for (int nn = 0; nn < 4; nn++)
                    #pragma unroll
                    for (int ss = 0; ss < 4; ss++)
                        scoreS[(4 * ng + nn) * 17 + 4 * shg + ss] = acc[nn][ss];
            }
        }
        __syncthreads();

        // ---- softmax: warp 0, 16 sh x 2 node-halves ----
        if (t < 32) {
            int sh = t & 15;
            int nlo = (t >> 4) * 16;
            int nhi = min(tn, nlo + 16);
            float m = -1e30f;
            for (int n = nlo; n < nhi; n++)
                m = fmaxf(m, scoreS[n * 17 + sh]);
            m = fmaxf(m, __shfl_xor_sync(0xffffffffu, m, 16));
            float nm = fmaxf(runm, m);
            float rf = __expf(runm - nm);
            float ssum = 0.f;
            for (int n = nlo; n < nhi; n++) {
                float e = __expf(scoreS[n * 17 + sh] - nm);
                scE[n * 16 + sh] = e;
                ssum += e;
            }
            ssum += __shfl_xor_sync(0xffffffffu, ssum, 16);
            runs = runs * rf + ssum;
            runm = nm;
            if (t < 16) rfac[t] = rf;
        }
        __syncthreads();

        // ---- y-pass: thread = column ----
        #pragma unroll
        for (int sh = 0; sh < 16; sh++) y[sh] *= rfac[sh];
        {
            const float4* eE = (const float4*)scE;
            const float* xcol = xs + bi * 8320 + t;
            #pragma unroll 8
            for (int n = 0; n < tn; n++) {
                float xv = xcol[n * 260];
                float4 e0 = eE[n * 4], e1 = eE[n * 4 + 1], e2 = eE[n * 4 + 2], e3 = eE[n * 4 + 3];
                y[0]  += e0.x * xv; y[1]  += e0.y * xv; y[2]  += e0.z * xv; y[3]  += e0.w * xv;
                y[4]  += e1.x * xv; y[5]  += e1.y * xv; y[6]  += e1.z * xv; y[7]  += e1.w * xv;
                y[8]  += e2.x * xv; y[9]  += e2.y * xv; y[10] += e2.z * xv; y[11] += e2.w * xv;
                y[12] += e3.x * xv; y[13] += e3.y * xv; y[14] += e3.z * xv; y[15] += e3.w * xv;
            }
        }
        // next-iteration top barrier doubles as the post-y fence
    }
    __syncthreads();

    if (t < 16) {
        g_cmax[bid * 16 + t] = runm;
        g_csum[bid * 16 + t] = runs;
    }
    #pragma unroll
    for (int sh = 0; sh < 16; sh++)
        g_cy[(bid * 16 + sh) * 256 + t] = y[sh];
}

// ---------------- combine: G=4 graphs/block --------------------------------------
// dyn smem floats: ysP[16384] att[4096] hbuf[1024] scl[256] itot[64] = 21824
#define COMB_SMEM_F 21824
__global__ __launch_bounds__(256) void k_comb(float* __restrict__ out,
                                              const float* __restrict__ fc1b,
                                              const float* __restrict__ fc2b)
{
    extern __shared__ __align__(16) float smc[];
    float* ysP  = smc;            // [g][h][j][s] as float4 over s
    float* att  = smc + 16384;    // [g][s*256+i]
    float* hbuf = smc + 20480;
    float* scl  = smc + 21504;    // [g*4+c][sh]
    float* itot = smc + 21760;

    int t = threadIdx.x;
    int b0 = blockIdx.x * 4;

    for (int g = 0; g < 4; g++) {
        int b = b0 + g;
        int cntb = g_off[b + 1] - g_off[b];
        int nch = min(4, (cntb + CHUNK - 1) >> 9);
        if (t < 16) {
            float M = -1e30f;
            for (int c = 0; c < nch; c++) M = fmaxf(M, g_cmax[(b * 4 + c) * 16 + t]);
            float tot = 0.f;
            #pragma unroll
            for (int c = 0; c < 4; c++) {
                float e = 0.f;
                if (c < nch) {
                    float s = g_csum[(b * 4 + c) * 16 + t];
                    if (s > 0.f) { e = __expf(g_cmax[(b * 4 + c) * 16 + t] - M); tot += e * s; }
                }
                scl[(g * 4 + c) * 16 + t] = e;
            }
            itot[g * 16 + t] = 1.f / tot;
        }
    }
    __syncthreads();

    for (int g = 0; g < 4; g++) {
        int b = b0 + g;
        #pragma unroll
        for (int sh = 0; sh < 16; sh++) {
            float acc = 0.f;
            #pragma unroll
            for (int c = 0; c < 4; c++)
                acc += scl[(g * 4 + c) * 16 + sh] * g_cy[((b * 4 + c) * 16 + sh) * 256 + t];
            float yv = acc * itot[g * 16 + sh];
            ysP[(((g * 4 + (sh & 3)) * 256 + t) << 2) + (sh >> 2)] = yv;
        }
    }
    __syncthreads();

    // attended for column i=t: a[g*4+s]
    float a[16];
    float ca = g_cAtt[t];
    #pragma unroll
    for (int i = 0; i < 16; i++) a[i] = ca;
    #pragma unroll
    for (int h = 0; h < 4; h++) {
        const float* wp = g_W2T + h * 65536 + t;
        const float4* y0 = (const float4*)ysP + (0 * 4 + h) * 256;
        const float4* y1 = (const float4*)ysP + (1 * 4 + h) * 256;
        const float4* y2 = (const float4*)ysP + (2 * 4 + h) * 256;
        const float4* y3 = (const float4*)ysP + (3 * 4 + h) * 256;
        #pragma unroll 8
        for (int j = 0; j < 256; j++) {
            float w = wp[j * 256];
            float4 p0 = y0[j], p1 = y1[j], p2 = y2[j], p3 = y3[j];
            a[0]  += w * p0.x; a[1]  += w * p0.y; a[2]  += w * p0.z; a[3]  += w * p0.w;
            a[4]  += w * p1.x; a[5]  += w * p1.y; a[6]  += w * p1.z; a[7]  += w * p1.w;
            a[8]  += w * p2.x; a[9]  += w * p2.y; a[10] += w * p2.z; a[11] += w * p2.w;
            a[12] += w * p3.x; a[13] += w * p3.y; a[14] += w * p3.z; a[15] += w * p3.w;
        }
    }
    #pragma unroll
    for (int g = 0; g < 4; g++)
        #pragma unroll
        for (int s = 0; s < 4; s++)
            att[g * 1024 + s * 256 + t] = a[g * 4 + s];
    __syncthreads();

    float pre[4];
    #pragma unroll
    for (int g = 0; g < 4; g++) pre[g] = fc1b[t];
    #pragma unroll 8
    for (int j = 0; j < 1024; j++) {
        float w = g_fc1T[j * 256 + t];
        #pragma unroll
        for (int g = 0; g < 4; g++) pre[g] += w * att[g * 1024 + j];
    }
    #pragma unroll
    for (int g = 0; g < 4; g++)
        hbuf[g * 256 + t] = 0.5f * pre[g] * (1.f + erff(pre[g] * 0.70710678118f));
    __syncthreads();

    float o[4];
    #pragma unroll
    for (int g = 0; g < 4; g++) o[g] = fc2b[t];
    #pragma unroll 8
    for (int j = 0; j < 256; j++) {
        float w = g_fc2T[j * 256 + t];
        #pragma unroll
        for (int g = 0; g < 4; g++) o[g] += w * hbuf[g * 256 + j];
    }
    #pragma unroll
    for (int g = 0; g < 4; g++)
        out[(b0 + g) * 256 + t] = o[g];
}

// ---------------- launch --------------------------------------------------------
extern "C" void kernel_launch(void* const* d_in, const int* in_sizes, int n_in,
                              void* d_out, int out_size)
{
    const float* X     = (const float*)d_in[0];
    const int*   cnt   = (const int*)  d_in[1];
    const float* seeds = (const float*)d_in[2];
    const float* inW   = (const float*)d_in[3];
    const float* inB   = (const float*)d_in[4];
    const float* outW  = (const float*)d_in[5];
    const float* outB  = (const float*)d_in[6];
    const float* fc1w  = (const float*)d_in[7];
    const float* fc1b  = (const float*)d_in[8];
    const float* fc2w  = (const float*)d_in[9];
    const float* fc2b  = (const float*)d_in[10];
    float* out = (float*)d_out;

    cudaFuncSetAttribute(k_attn, cudaFuncAttributeMaxDynamicSharedMemorySize,
                         ATTN_SMEM_F * 4);
    cudaFuncSetAttribute(k_comb, cudaFuncAttributeMaxDynamicSharedMemorySize,
                         COMB_SMEM_F * 4);

    k_pro<<<609, 256>>>(cnt, seeds, inW, inB, outW, outB, fc1w, fc2w);
    k_attn<<<1024, 256, ATTN_SMEM_F * 4>>>(X);
    k_comb<<<64, 256, COMB_SMEM_F * 4>>>(out, fc1b, fc2b);
}